// round 16
// baseline (speedup 1.0000x reference)
#include <cuda_runtime.h>
#include <cuda_bf16.h>
#include <math.h>
#include <cstdint>

#define N_ROWS 16384
#define K_CB   4096
#define D_DIM  256

// u16 logit encoding: q = round(-logit * QS), logit in [-40, 0]
#define QS    1638.375f            // 65535 / 40
#define QINV  (-6.1036087e-4f)     // -1/QS  (decode: logit = q * QINV)

__device__ float g_xn[N_ROWS * D_DIM];
__device__ float g_cbn[K_CB * D_DIM];
__device__ __nv_bfloat16 g_xh[N_ROWS * D_DIM];
__device__ __nv_bfloat16 g_xl[N_ROWS * D_DIM];
__device__ __nv_bfloat16 g_cbh[K_CB * D_DIM];
__device__ __nv_bfloat16 g_cbl[K_CB * D_DIM];
__device__ __align__(16) unsigned short g_q[(size_t)N_ROWS * K_CB];  // u16 logits
__device__ float g_loss_partial[N_ROWS];
__device__ int   g_counts[K_CB];

__device__ __forceinline__ uint32_t smem_u32(const void* p) {
    uint32_t a;
    asm("{ .reg .u64 t; cvta.to.shared.u64 t, %1; cvt.u32.u64 %0, t; }" : "=r"(a) : "l"(p));
    return a;
}

// ===================== reductions ==========================================
__device__ __forceinline__ float block_reduce_sum256(float v, float* sh8) {
    const int t = threadIdx.x;
    #pragma unroll
    for (int o = 16; o > 0; o >>= 1) v += __shfl_xor_sync(0xffffffffu, v, o);
    const int warp = t >> 5, lane = t & 31;
    if (lane == 0) sh8[warp] = v;
    __syncthreads();
    if (warp == 0) {
        float x = (lane < 8) ? sh8[lane] : 0.0f;
        #pragma unroll
        for (int o = 4; o > 0; o >>= 1) x += __shfl_xor_sync(0xffffffffu, x, o);
        if (lane == 0) sh8[0] = x;
    }
    __syncthreads();
    float r = sh8[0];
    __syncthreads();
    return r;
}
__device__ __forceinline__ void block_reduce_maxsum256(float m, float s,
                                                       float* shm, float* shs,
                                                       float* out_m, float* out_s) {
    const int t = threadIdx.x;
    #pragma unroll
    for (int o = 16; o > 0; o >>= 1) {
        m = fmaxf(m, __shfl_xor_sync(0xffffffffu, m, o));
        s += __shfl_xor_sync(0xffffffffu, s, o);
    }
    const int warp = t >> 5, lane = t & 31;
    if (lane == 0) { shm[warp] = m; shs[warp] = s; }
    __syncthreads();
    if (warp == 0) {
        float xm = (lane < 8) ? shm[lane] : -1e30f;
        float xs = (lane < 8) ? shs[lane] : 0.0f;
        #pragma unroll
        for (int o = 4; o > 0; o >>= 1) {
            xm = fmaxf(xm, __shfl_xor_sync(0xffffffffu, xm, o));
            xs += __shfl_xor_sync(0xffffffffu, xs, o);
        }
        if (lane == 0) { shm[0] = xm; shs[0] = xs; }
    }
    __syncthreads();
    *out_m = shm[0];
    *out_s = shs[0];
    __syncthreads();
}
__device__ __forceinline__ double block_reduce_sum256_d(double v, double* shd8) {
    const int t = threadIdx.x;
    #pragma unroll
    for (int o = 16; o > 0; o >>= 1) v += __shfl_xor_sync(0xffffffffu, v, o);
    const int warp = t >> 5, lane = t & 31;
    if (lane == 0) shd8[warp] = v;
    __syncthreads();
    if (warp == 0) {
        double x = (lane < 8) ? shd8[lane] : 0.0;
        #pragma unroll
        for (int o = 4; o > 0; o >>= 1) x += __shfl_xor_sync(0xffffffffu, x, o);
        if (lane == 0) shd8[0] = x;
    }
    __syncthreads();
    double r = shd8[0];
    __syncthreads();
    return r;
}
__device__ __forceinline__ float block_reduce_sum1024(float v, float* sh32) {
    const int t = threadIdx.x;
    #pragma unroll
    for (int o = 16; o > 0; o >>= 1) v += __shfl_xor_sync(0xffffffffu, v, o);
    const int warp = t >> 5, lane = t & 31;
    if (lane == 0) sh32[warp] = v;
    __syncthreads();
    if (warp == 0) {
        float x = sh32[lane];
        #pragma unroll
        for (int o = 16; o > 0; o >>= 1) x += __shfl_xor_sync(0xffffffffu, x, o);
        if (lane == 0) sh32[0] = x;
    }
    __syncthreads();
    float r = sh32[0];
    __syncthreads();
    return r;
}

// ===================== normalize: warp-per-row =============================
__global__ __launch_bounds__(256)
void normalize_all_kernel(const float* __restrict__ inputs,
                          const float* __restrict__ codebook) {
    const int t = threadIdx.x;
    const int warp = t >> 5, lane = t & 31;
    const int grow = (blockIdx.x << 3) + warp;
    const bool is_cb = (grow < K_CB);
    const int row = is_cb ? grow : (grow - K_CB);
    const float* src = (is_cb ? codebook : inputs) + (size_t)row * D_DIM + (lane << 3);

    const float4 v0 = ((const float4*)src)[0];
    const float4 v1 = ((const float4*)src)[1];
    float ss = v0.x * v0.x + v0.y * v0.y + v0.z * v0.z + v0.w * v0.w
             + v1.x * v1.x + v1.y * v1.y + v1.z * v1.z + v1.w * v1.w;
    #pragma unroll
    for (int o = 16; o > 0; o >>= 1) ss += __shfl_xor_sync(0xffffffffu, ss, o);

    const float inv = 1.0f / fmaxf(sqrtf(ss), 1e-12f);
    float q[8] = {v0.x * inv, v0.y * inv, v0.z * inv, v0.w * inv,
                  v1.x * inv, v1.y * inv, v1.z * inv, v1.w * inv};
    __nv_bfloat16 h8[8], l8[8];
    #pragma unroll
    for (int i = 0; i < 8; i++) {
        h8[i] = __float2bfloat16(q[i]);
        l8[i] = __float2bfloat16(q[i] - __bfloat162float(h8[i]));
    }
    const size_t off = (size_t)row * D_DIM + (lane << 3);
    float* qdst = (is_cb ? g_cbn : g_xn) + off;
    ((float4*)qdst)[0] = make_float4(q[0], q[1], q[2], q[3]);
    ((float4*)qdst)[1] = make_float4(q[4], q[5], q[6], q[7]);
    *(uint4*)((is_cb ? g_cbh : g_xh) + off) = *(const uint4*)h8;
    *(uint4*)((is_cb ? g_cbl : g_xl) + off) = *(const uint4*)l8;
    if (is_cb && lane == 0) g_counts[row] = 0;
}

// ===================== cp.async pipelined split-bf16 GEMM ==================
// g_q[m,n] = u16 round(-(20*dot - 20) * QS), clamped to [0, 65535]
#define SA 72
#define TILE_B (128 * SA * 2)
#define STAGE_B (2 * TILE_B)
#define GEMM_SMEM (3 * STAGE_B)

__device__ __forceinline__ void cp16(uint32_t saddr, const void* gptr) {
    asm volatile("cp.async.cg.shared.global [%0], [%1], 16;"
                 :: "r"(saddr), "l"(__cvta_generic_to_global(gptr)));
}

__device__ __forceinline__ unsigned short enc_logit(float acc) {
    const float logit = fmaf(20.0f, acc, -20.0f);
    // -logit*QS in [0, 65535]; logit>0 (bf16 noise) clamps to 0
    const float qf = fminf(fmaxf(-logit * QS, 0.0f), 65535.0f);
    return (unsigned short)__float2uint_rn(qf);
}

__global__ __launch_bounds__(256, 2)
void gemm_tc_kernel() {
    extern __shared__ char sm[];
    const uint32_t sbase = smem_u32(sm);

    const int t = threadIdx.x;
    const int wid = t >> 5, lane = t & 31;
    const int g = lane >> 2, tig = lane & 3;
    const int warpM = wid & 1;
    const int warpN = wid >> 1;
    const int m0 = blockIdx.y << 7;
    const int n0 = blockIdx.x << 7;

    const int lsel = lane & 15;
    const int ksel = (lane >> 4) << 3;

    float acc[4][4][4];
    #pragma unroll
    for (int i = 0; i < 4; i++)
        #pragma unroll
        for (int j = 0; j < 4; j++)
            #pragma unroll
            for (int c = 0; c < 4; c++) acc[i][j][c] = 0.0f;

    auto issue_stage = [&](int stage, int kt) {
        const int phase = kt >> 2;
        const int d0 = (kt & 3) << 6;
        const __nv_bfloat16* Asrc = (phase == 2) ? g_xl  : g_xh;
        const __nv_bfloat16* Bsrc = (phase == 1) ? g_cbl : g_cbh;
        const uint32_t sa = sbase + stage * STAGE_B;
        const uint32_t sb = sa + TILE_B;
        #pragma unroll
        for (int j = 0; j < 4; j++) {
            const int c = t + (j << 8);
            const int row = c >> 3, sub = c & 7;
            cp16(sa + row * (SA * 2) + sub * 16,
                 Asrc + (size_t)(m0 + row) * D_DIM + d0 + sub * 8);
            cp16(sb + row * (SA * 2) + sub * 16,
                 Bsrc + (size_t)(n0 + row) * D_DIM + d0 + sub * 8);
        }
        asm volatile("cp.async.commit_group;");
    };

    issue_stage(0, 0);
    issue_stage(1, 1);

    #pragma unroll 1
    for (int kt = 0; kt < 12; kt++) {
        if (kt < 11) asm volatile("cp.async.wait_group 1;");
        else         asm volatile("cp.async.wait_group 0;");
        __syncthreads();

        if (kt < 10) {
            const int ns = (kt + 2) - ((kt + 2) / 3) * 3;
            issue_stage(ns, kt + 2);
        }

        const int stage = kt - (kt / 3) * 3;
        const uint32_t sa = sbase + stage * STAGE_B;
        const uint32_t sb = sa + TILE_B;

        #pragma unroll
        for (int k0 = 0; k0 < 64; k0 += 16) {
            uint32_t af[4][4], bfr[4][2];
            #pragma unroll
            for (int mt = 0; mt < 4; mt++) {
                const uint32_t aaddr = sa
                    + (warpM * 64 + mt * 16 + lsel) * (SA * 2) + (k0 + ksel) * 2;
                asm volatile(
                    "ldmatrix.sync.aligned.m8n8.x4.shared.b16 {%0,%1,%2,%3}, [%4];"
                    : "=r"(af[mt][0]), "=r"(af[mt][1]), "=r"(af[mt][2]), "=r"(af[mt][3])
                    : "r"(aaddr));
            }
            #pragma unroll
            for (int np = 0; np < 2; np++) {
                const uint32_t baddr = sb
                    + (warpN * 32 + np * 16 + lsel) * (SA * 2) + (k0 + ksel) * 2;
                asm volatile(
                    "ldmatrix.sync.aligned.m8n8.x4.shared.b16 {%0,%1,%2,%3}, [%4];"
                    : "=r"(bfr[2 * np][0]), "=r"(bfr[2 * np + 1][0]),
                      "=r"(bfr[2 * np][1]), "=r"(bfr[2 * np + 1][1])
                    : "r"(baddr));
            }
            #pragma unroll
            for (int mt = 0; mt < 4; mt++)
                #pragma unroll
                for (int nt = 0; nt < 4; nt++)
                    asm volatile(
                        "mma.sync.aligned.m16n8k16.row.col.f32.bf16.bf16.f32 "
                        "{%0,%1,%2,%3}, {%4,%5,%6,%7}, {%8,%9}, {%0,%1,%2,%3};"
                        : "+f"(acc[mt][nt][0]), "+f"(acc[mt][nt][1]),
                          "+f"(acc[mt][nt][2]), "+f"(acc[mt][nt][3])
                        : "r"(af[mt][0]), "r"(af[mt][1]), "r"(af[mt][2]), "r"(af[mt][3]),
                          "r"(bfr[nt][0]), "r"(bfr[nt][1]));
        }
    }

    // epilogue: u16 logit pairs (cc even => 4B-aligned ushort2)
    #pragma unroll
    for (int mt = 0; mt < 4; mt++) {
        #pragma unroll
        for (int nt = 0; nt < 4; nt++) {
            const int r  = m0 + warpM * 64 + mt * 16 + g;
            const int cc = n0 + warpN * 32 + nt * 8 + tig * 2;
            ushort2 p0, p1;
            p0.x = enc_logit(acc[mt][nt][0]);
            p0.y = enc_logit(acc[mt][nt][1]);
            p1.x = enc_logit(acc[mt][nt][2]);
            p1.y = enc_logit(acc[mt][nt][3]);
            *(ushort2*)(g_q + (size_t)r * K_CB + cc)       = p0;
            *(ushort2*)(g_q + (size_t)(r + 8) * K_CB + cc) = p1;
        }
    }
}

// ===================== softmax / argmin / gather ===========================
#define MAX_CAND 64

__global__ __launch_bounds__(256)
void softmax_row_kernel(float* __restrict__ probs,
                        float* __restrict__ quant,
                        float* __restrict__ idx_out) {
    __shared__ float  xrow[256];
    __shared__ float  shm[8], shs[8];
    __shared__ double shd8[8];
    __shared__ int    cand[MAX_CAND];
    __shared__ double cdist[MAX_CAND];
    __shared__ int    ncand;
    __shared__ int    ridx_sh;

    const int n = blockIdx.x, t = threadIdx.x;
    const unsigned short* qrow = g_q + (size_t)n * K_CB;
    float* prow = probs + (size_t)n * K_CB;

    xrow[t] = g_xn[n * D_DIM + t];
    if (t == 0) ncand = 0;

    // thread t covers u16s 8t..8t+7 and 2048+8t..2048+8t+7
    float ev[16];
    float emax = 0.0f, esum = 0.0f;
    #pragma unroll
    for (int i = 0; i < 2; i++) {
        const uint4 raw = *(const uint4*)(qrow + (t << 3) + (i << 11));
        const unsigned short* u = (const unsigned short*)&raw;
        #pragma unroll
        for (int j = 0; j < 8; j++) {
            const float e = __expf((float)u[j] * QINV);
            ev[i * 8 + j] = e;
            emax = fmaxf(e, emax);
            esum += e;
        }
    }
    float evmax, tot;
    block_reduce_maxsum256(emax, esum, shm, shs, &evmax, &tot);

    const float inv = 1.0f / tot;
    #pragma unroll
    for (int i = 0; i < 2; i++)
        #pragma unroll
        for (int j = 0; j < 8; j++)
            prow[(t << 3) + (i << 11) + j] = ev[i * 8 + j] * inv;

    // candidate window: ln(1/0.9965)=3.5e-3 > 2x u16 quant (1.2e-3) + GEMM noise
    const float cthresh = evmax * 0.9965f;
    #pragma unroll
    for (int i = 0; i < 16; i++) {
        if (ev[i] >= cthresh) {
            const int p = atomicAdd(&ncand, 1);
            if (p < MAX_CAND) cand[p] = (t << 3) + ((i >> 3) << 11) + (i & 7);
        }
    }
    __syncthreads();
    const int nc = min(ncand, MAX_CAND);

    for (int c = 0; c < nc; c++) {
        const int k = cand[c];
        const double prod = (double)xrow[t] * (double)g_cbn[(size_t)k * D_DIM + t];
        const double s = block_reduce_sum256_d(prod, shd8);
        if (t == 0) cdist[c] = 2.0 - 2.0 * s;
    }
    __syncthreads();

    if (t == 0) {
        double dmin = 1e30;
        for (int c = 0; c < nc; c++) dmin = fmin(dmin, cdist[c]);
        int bi = 0x7fffffff;
        for (int c = 0; c < nc; c++)
            if (cdist[c] <= dmin + 4e-7) bi = min(bi, cand[c]);
        ridx_sh = bi;
    }
    __syncthreads();

    const int ridx = ridx_sh;
    const float xv = xrow[t];
    const float cv = g_cbn[(size_t)ridx * D_DIM + t];
    quant[(size_t)n * D_DIM + t] = xv + (cv - xv);
    const float d = cv - xv;
    const float lp = block_reduce_sum256(d * d, shm);
    if (t == 0) {
        g_loss_partial[n] = lp;
        atomicAdd(&g_counts[ridx], 1);
        idx_out[n] = (float)ridx;
    }
}

// ===================== finalize ============================================
__global__ __launch_bounds__(1024)
void finalize_kernel(float* __restrict__ out_loss,
                     float* __restrict__ out_perp) {
    __shared__ float sh32[32];
    const int t = threadIdx.x;
    float s = 0.0f;
    #pragma unroll
    for (int i = 0; i < 4; i++) {
        const float4 v = *(const float4*)(g_loss_partial + (t << 2) + (i << 12));
        s += (v.x + v.y) + (v.z + v.w);
    }
    const float tot = block_reduce_sum1024(s, sh32);

    float e = 0.0f;
    const int4 cv = *(const int4*)(g_counts + (t << 2));
    const float invN = 1.0f / (float)N_ROWS;
    {
        const float p0 = (float)cv.x * invN, p1 = (float)cv.y * invN;
        const float p2 = (float)cv.z * invN, p3 = (float)cv.w * invN;
        e = p0 * logf(p0 + 1e-10f) + p1 * logf(p1 + 1e-10f)
          + p2 * logf(p2 + 1e-10f) + p3 * logf(p3 + 1e-10f);
    }
    const float esum = block_reduce_sum1024(e, sh32);

    if (t == 0) {
        *out_loss = 0.25f * (tot / (float)((size_t)N_ROWS * D_DIM));
        *out_perp = expf(-esum);
    }
}

// ===========================================================================
extern "C" void kernel_launch(void* const* d_in, const int* in_sizes, int n_in,
                              void* d_out, int out_size) {
    const float* inputs   = (const float*)d_in[0];
    const float* codebook = (const float*)d_in[1];

    float* out       = (float*)d_out;
    float* out_loss  = out;
    float* out_quant = out + 1;
    float* out_probs = out_quant + (size_t)N_ROWS * D_DIM;
    float* out_perp  = out_probs + (size_t)N_ROWS * K_CB;
    float* out_idx   = out_perp + 1;

    cudaFuncSetAttribute(gemm_tc_kernel,
                         cudaFuncAttributeMaxDynamicSharedMemorySize, GEMM_SMEM);

    normalize_all_kernel<<<(K_CB + N_ROWS) / 8, 256>>>(inputs, codebook);

    dim3 grid(K_CB / 128, N_ROWS / 128);   // (32, 128)
    gemm_tc_kernel<<<grid, 256, GEMM_SMEM>>>();

    softmax_row_kernel<<<N_ROWS, 256>>>(out_probs, out_quant, out_idx);
    finalize_kernel<<<1, 1024>>>(out_loss, out_perp);
}

// round 17
// speedup vs baseline: 1.0099x; 1.0099x over previous
#include <cuda_runtime.h>
#include <cuda_bf16.h>
#include <math.h>
#include <cstdint>

#define N_ROWS 16384
#define K_CB   4096
#define D_DIM  256

// u16 logit encoding: q = round(-logit * QS), logit in [-40, 0]
#define QS    1638.375f            // 65535 / 40
#define QINV  (-6.1036087e-4f)     // -1/QS

__device__ float g_xn[N_ROWS * D_DIM];
__device__ float g_cbn[K_CB * D_DIM];
__device__ __nv_bfloat16 g_xh[N_ROWS * D_DIM];
__device__ __nv_bfloat16 g_xl[N_ROWS * D_DIM];
__device__ __nv_bfloat16 g_cbh[K_CB * D_DIM];
__device__ __nv_bfloat16 g_cbl[K_CB * D_DIM];
__device__ __align__(16) unsigned short g_q[(size_t)N_ROWS * K_CB];
__device__ float g_loss_partial[N_ROWS];
__device__ int   g_counts[K_CB];

__device__ __forceinline__ uint32_t smem_u32(const void* p) {
    uint32_t a;
    asm("{ .reg .u64 t; cvta.to.shared.u64 t, %1; cvt.u32.u64 %0, t; }" : "=r"(a) : "l"(p));
    return a;
}

// ===================== reductions ==========================================
__device__ __forceinline__ float block_reduce_sum256(float v, float* sh8) {
    const int t = threadIdx.x;
    #pragma unroll
    for (int o = 16; o > 0; o >>= 1) v += __shfl_xor_sync(0xffffffffu, v, o);
    const int warp = t >> 5, lane = t & 31;
    if (lane == 0) sh8[warp] = v;
    __syncthreads();
    if (warp == 0) {
        float x = (lane < 8) ? sh8[lane] : 0.0f;
        #pragma unroll
        for (int o = 4; o > 0; o >>= 1) x += __shfl_xor_sync(0xffffffffu, x, o);
        if (lane == 0) sh8[0] = x;
    }
    __syncthreads();
    float r = sh8[0];
    __syncthreads();
    return r;
}
__device__ __forceinline__ void block_reduce_maxsum256(float m, float s,
                                                       float* shm, float* shs,
                                                       float* out_m, float* out_s) {
    const int t = threadIdx.x;
    #pragma unroll
    for (int o = 16; o > 0; o >>= 1) {
        m = fmaxf(m, __shfl_xor_sync(0xffffffffu, m, o));
        s += __shfl_xor_sync(0xffffffffu, s, o);
    }
    const int warp = t >> 5, lane = t & 31;
    if (lane == 0) { shm[warp] = m; shs[warp] = s; }
    __syncthreads();
    if (warp == 0) {
        float xm = (lane < 8) ? shm[lane] : -1e30f;
        float xs = (lane < 8) ? shs[lane] : 0.0f;
        #pragma unroll
        for (int o = 4; o > 0; o >>= 1) {
            xm = fmaxf(xm, __shfl_xor_sync(0xffffffffu, xm, o));
            xs += __shfl_xor_sync(0xffffffffu, xs, o);
        }
        if (lane == 0) { shm[0] = xm; shs[0] = xs; }
    }
    __syncthreads();
    *out_m = shm[0];
    *out_s = shs[0];
    __syncthreads();
}
__device__ __forceinline__ double block_reduce_sum256_d(double v, double* shd8) {
    const int t = threadIdx.x;
    #pragma unroll
    for (int o = 16; o > 0; o >>= 1) v += __shfl_xor_sync(0xffffffffu, v, o);
    const int warp = t >> 5, lane = t & 31;
    if (lane == 0) shd8[warp] = v;
    __syncthreads();
    if (warp == 0) {
        double x = (lane < 8) ? shd8[lane] : 0.0;
        #pragma unroll
        for (int o = 4; o > 0; o >>= 1) x += __shfl_xor_sync(0xffffffffu, x, o);
        if (lane == 0) shd8[0] = x;
    }
    __syncthreads();
    double r = shd8[0];
    __syncthreads();
    return r;
}
__device__ __forceinline__ float block_reduce_sum1024(float v, float* sh32) {
    const int t = threadIdx.x;
    #pragma unroll
    for (int o = 16; o > 0; o >>= 1) v += __shfl_xor_sync(0xffffffffu, v, o);
    const int warp = t >> 5, lane = t & 31;
    if (lane == 0) sh32[warp] = v;
    __syncthreads();
    if (warp == 0) {
        float x = sh32[lane];
        #pragma unroll
        for (int o = 16; o > 0; o >>= 1) x += __shfl_xor_sync(0xffffffffu, x, o);
        if (lane == 0) sh32[0] = x;
    }
    __syncthreads();
    float r = sh32[0];
    __syncthreads();
    return r;
}

// ===================== normalize: warp-per-row =============================
__global__ __launch_bounds__(256)
void normalize_all_kernel(const float* __restrict__ inputs,
                          const float* __restrict__ codebook) {
    const int t = threadIdx.x;
    const int warp = t >> 5, lane = t & 31;
    const int grow = (blockIdx.x << 3) + warp;
    const bool is_cb = (grow < K_CB);
    const int row = is_cb ? grow : (grow - K_CB);
    const float* src = (is_cb ? codebook : inputs) + (size_t)row * D_DIM + (lane << 3);

    const float4 v0 = ((const float4*)src)[0];
    const float4 v1 = ((const float4*)src)[1];
    float ss = v0.x * v0.x + v0.y * v0.y + v0.z * v0.z + v0.w * v0.w
             + v1.x * v1.x + v1.y * v1.y + v1.z * v1.z + v1.w * v1.w;
    #pragma unroll
    for (int o = 16; o > 0; o >>= 1) ss += __shfl_xor_sync(0xffffffffu, ss, o);

    const float inv = 1.0f / fmaxf(sqrtf(ss), 1e-12f);
    float q[8] = {v0.x * inv, v0.y * inv, v0.z * inv, v0.w * inv,
                  v1.x * inv, v1.y * inv, v1.z * inv, v1.w * inv};
    __nv_bfloat16 h8[8], l8[8];
    #pragma unroll
    for (int i = 0; i < 8; i++) {
        h8[i] = __float2bfloat16(q[i]);
        l8[i] = __float2bfloat16(q[i] - __bfloat162float(h8[i]));
    }
    const size_t off = (size_t)row * D_DIM + (lane << 3);
    float* qdst = (is_cb ? g_cbn : g_xn) + off;
    ((float4*)qdst)[0] = make_float4(q[0], q[1], q[2], q[3]);
    ((float4*)qdst)[1] = make_float4(q[4], q[5], q[6], q[7]);
    *(uint4*)((is_cb ? g_cbh : g_xh) + off) = *(const uint4*)h8;
    *(uint4*)((is_cb ? g_cbl : g_xl) + off) = *(const uint4*)l8;
    if (is_cb && lane == 0) g_counts[row] = 0;
}

// ===================== cp.async pipelined split-bf16 GEMM ==================
// g_q[m,n] = u16 round(-(20*dot - 20) * QS); epilogue staged through smem
// for fully-coalesced 16B global stores (no partial-sector RMW).
#define SA 72
#define TILE_B (128 * SA * 2)
#define STAGE_B (2 * TILE_B)
#define GEMM_SMEM (3 * STAGE_B)          // 110592; epi staging aliases this
#define EPI_STRIDE 136                    // u16 row stride (272 B, 16B multiple)

__device__ __forceinline__ void cp16(uint32_t saddr, const void* gptr) {
    asm volatile("cp.async.cg.shared.global [%0], [%1], 16;"
                 :: "r"(saddr), "l"(__cvta_generic_to_global(gptr)));
}

__device__ __forceinline__ unsigned short enc_logit(float acc) {
    const float logit = fmaf(20.0f, acc, -20.0f);
    const float qf = fminf(fmaxf(-logit * QS, 0.0f), 65535.0f);
    return (unsigned short)__float2uint_rn(qf);
}

__global__ __launch_bounds__(256, 2)
void gemm_tc_kernel() {
    extern __shared__ char sm[];
    const uint32_t sbase = smem_u32(sm);

    const int t = threadIdx.x;
    const int wid = t >> 5, lane = t & 31;
    const int g = lane >> 2, tig = lane & 3;
    const int warpM = wid & 1;
    const int warpN = wid >> 1;
    const int m0 = blockIdx.y << 7;
    const int n0 = blockIdx.x << 7;

    const int lsel = lane & 15;
    const int ksel = (lane >> 4) << 3;

    float acc[4][4][4];
    #pragma unroll
    for (int i = 0; i < 4; i++)
        #pragma unroll
        for (int j = 0; j < 4; j++)
            #pragma unroll
            for (int c = 0; c < 4; c++) acc[i][j][c] = 0.0f;

    auto issue_stage = [&](int stage, int kt) {
        const int phase = kt >> 2;
        const int d0 = (kt & 3) << 6;
        const __nv_bfloat16* Asrc = (phase == 2) ? g_xl  : g_xh;
        const __nv_bfloat16* Bsrc = (phase == 1) ? g_cbl : g_cbh;
        const uint32_t sa = sbase + stage * STAGE_B;
        const uint32_t sb = sa + TILE_B;
        #pragma unroll
        for (int j = 0; j < 4; j++) {
            const int c = t + (j << 8);
            const int row = c >> 3, sub = c & 7;
            cp16(sa + row * (SA * 2) + sub * 16,
                 Asrc + (size_t)(m0 + row) * D_DIM + d0 + sub * 8);
            cp16(sb + row * (SA * 2) + sub * 16,
                 Bsrc + (size_t)(n0 + row) * D_DIM + d0 + sub * 8);
        }
        asm volatile("cp.async.commit_group;");
    };

    issue_stage(0, 0);
    issue_stage(1, 1);

    #pragma unroll 1
    for (int kt = 0; kt < 12; kt++) {
        if (kt < 11) asm volatile("cp.async.wait_group 1;");
        else         asm volatile("cp.async.wait_group 0;");
        __syncthreads();

        if (kt < 10) {
            const int ns = (kt + 2) - ((kt + 2) / 3) * 3;
            issue_stage(ns, kt + 2);
        }

        const int stage = kt - (kt / 3) * 3;
        const uint32_t sa = sbase + stage * STAGE_B;
        const uint32_t sb = sa + TILE_B;

        #pragma unroll
        for (int k0 = 0; k0 < 64; k0 += 16) {
            uint32_t af[4][4], bfr[4][2];
            #pragma unroll
            for (int mt = 0; mt < 4; mt++) {
                const uint32_t aaddr = sa
                    + (warpM * 64 + mt * 16 + lsel) * (SA * 2) + (k0 + ksel) * 2;
                asm volatile(
                    "ldmatrix.sync.aligned.m8n8.x4.shared.b16 {%0,%1,%2,%3}, [%4];"
                    : "=r"(af[mt][0]), "=r"(af[mt][1]), "=r"(af[mt][2]), "=r"(af[mt][3])
                    : "r"(aaddr));
            }
            #pragma unroll
            for (int np = 0; np < 2; np++) {
                const uint32_t baddr = sb
                    + (warpN * 32 + np * 16 + lsel) * (SA * 2) + (k0 + ksel) * 2;
                asm volatile(
                    "ldmatrix.sync.aligned.m8n8.x4.shared.b16 {%0,%1,%2,%3}, [%4];"
                    : "=r"(bfr[2 * np][0]), "=r"(bfr[2 * np + 1][0]),
                      "=r"(bfr[2 * np][1]), "=r"(bfr[2 * np + 1][1])
                    : "r"(baddr));
            }
            #pragma unroll
            for (int mt = 0; mt < 4; mt++)
                #pragma unroll
                for (int nt = 0; nt < 4; nt++)
                    asm volatile(
                        "mma.sync.aligned.m16n8k16.row.col.f32.bf16.bf16.f32 "
                        "{%0,%1,%2,%3}, {%4,%5,%6,%7}, {%8,%9}, {%0,%1,%2,%3};"
                        : "+f"(acc[mt][nt][0]), "+f"(acc[mt][nt][1]),
                          "+f"(acc[mt][nt][2]), "+f"(acc[mt][nt][3])
                        : "r"(af[mt][0]), "r"(af[mt][1]), "r"(af[mt][2]), "r"(af[mt][3]),
                          "r"(bfr[nt][0]), "r"(bfr[nt][1]));
        }
    }

    // ---- epilogue: stage u16 tile in smem, drain with coalesced uint4 ----
    __syncthreads();                           // mainloop smem reads done
    unsigned short* epi = (unsigned short*)sm; // 128 x EPI_STRIDE u16 = 34.8KB
    #pragma unroll
    for (int mt = 0; mt < 4; mt++) {
        #pragma unroll
        for (int nt = 0; nt < 4; nt++) {
            const int r  = warpM * 64 + mt * 16 + g;
            const int cc = warpN * 32 + nt * 8 + tig * 2;
            ushort2 p0, p1;
            p0.x = enc_logit(acc[mt][nt][0]);
            p0.y = enc_logit(acc[mt][nt][1]);
            p1.x = enc_logit(acc[mt][nt][2]);
            p1.y = enc_logit(acc[mt][nt][3]);
            *(ushort2*)(epi + r * EPI_STRIDE + cc)       = p0;   // conflict-free
            *(ushort2*)(epi + (r + 8) * EPI_STRIDE + cc) = p1;
        }
    }
    __syncthreads();
    // 2048 chunks of 16B: chunk c -> row c>>4, col-offset (c&15)*8 u16
    #pragma unroll
    for (int j = 0; j < 8; j++) {
        const int c = t + (j << 8);
        const int row = c >> 4, off = (c & 15) << 3;
        const uint4 v = *(const uint4*)(epi + row * EPI_STRIDE + off);
        *(uint4*)(g_q + (size_t)(m0 + row) * K_CB + n0 + off) = v;
    }
}

// ===================== softmax / argmin / gather ===========================
#define MAX_CAND 64

__global__ __launch_bounds__(256)
void softmax_row_kernel(float* __restrict__ probs,
                        float* __restrict__ quant,
                        float* __restrict__ idx_out) {
    __shared__ float  xrow[256];
    __shared__ float  shm[8], shs[8];
    __shared__ double shd8[8];
    __shared__ int    cand[MAX_CAND];
    __shared__ double cdist[MAX_CAND];
    __shared__ int    ncand;
    __shared__ int    ridx_sh;

    const int n = blockIdx.x, t = threadIdx.x;
    const unsigned short* qrow = g_q + (size_t)n * K_CB;
    float* prow = probs + (size_t)n * K_CB;

    xrow[t] = g_xn[n * D_DIM + t];
    if (t == 0) ncand = 0;

    float ev[16];
    float emax = 0.0f, esum = 0.0f;
    #pragma unroll
    for (int i = 0; i < 2; i++) {
        const uint4 raw = *(const uint4*)(qrow + (t << 3) + (i << 11));
        const unsigned short* u = (const unsigned short*)&raw;
        #pragma unroll
        for (int j = 0; j < 8; j++) {
            const float e = __expf((float)u[j] * QINV);
            ev[i * 8 + j] = e;
            emax = fmaxf(e, emax);
            esum += e;
        }
    }
    float evmax, tot;
    block_reduce_maxsum256(emax, esum, shm, shs, &evmax, &tot);

    const float inv = 1.0f / tot;
    #pragma unroll
    for (int i = 0; i < 2; i++)
        #pragma unroll
        for (int j = 0; j < 8; j++)
            prow[(t << 3) + (i << 11) + j] = ev[i * 8 + j] * inv;

    const float cthresh = evmax * 0.9965f;
    #pragma unroll
    for (int i = 0; i < 16; i++) {
        if (ev[i] >= cthresh) {
            const int p = atomicAdd(&ncand, 1);
            if (p < MAX_CAND) cand[p] = (t << 3) + ((i >> 3) << 11) + (i & 7);
        }
    }
    __syncthreads();
    const int nc = min(ncand, MAX_CAND);

    for (int c = 0; c < nc; c++) {
        const int k = cand[c];
        const double prod = (double)xrow[t] * (double)g_cbn[(size_t)k * D_DIM + t];
        const double s = block_reduce_sum256_d(prod, shd8);
        if (t == 0) cdist[c] = 2.0 - 2.0 * s;
    }
    __syncthreads();

    if (t == 0) {
        double dmin = 1e30;
        for (int c = 0; c < nc; c++) dmin = fmin(dmin, cdist[c]);
        int bi = 0x7fffffff;
        for (int c = 0; c < nc; c++)
            if (cdist[c] <= dmin + 4e-7) bi = min(bi, cand[c]);
        ridx_sh = bi;
    }
    __syncthreads();

    const int ridx = ridx_sh;
    const float xv = xrow[t];
    const float cv = g_cbn[(size_t)ridx * D_DIM + t];
    quant[(size_t)n * D_DIM + t] = xv + (cv - xv);
    const float d = cv - xv;
    const float lp = block_reduce_sum256(d * d, shm);
    if (t == 0) {
        g_loss_partial[n] = lp;
        atomicAdd(&g_counts[ridx], 1);
        idx_out[n] = (float)ridx;
    }
}

// ===================== finalize ============================================
__global__ __launch_bounds__(1024)
void finalize_kernel(float* __restrict__ out_loss,
                     float* __restrict__ out_perp) {
    __shared__ float sh32[32];
    const int t = threadIdx.x;
    float s = 0.0f;
    #pragma unroll
    for (int i = 0; i < 4; i++) {
        const float4 v = *(const float4*)(g_loss_partial + (t << 2) + (i << 12));
        s += (v.x + v.y) + (v.z + v.w);
    }
    const float tot = block_reduce_sum1024(s, sh32);

    float e = 0.0f;
    const int4 cv = *(const int4*)(g_counts + (t << 2));
    const float invN = 1.0f / (float)N_ROWS;
    {
        const float p0 = (float)cv.x * invN, p1 = (float)cv.y * invN;
        const float p2 = (float)cv.z * invN, p3 = (float)cv.w * invN;
        e = p0 * logf(p0 + 1e-10f) + p1 * logf(p1 + 1e-10f)
          + p2 * logf(p2 + 1e-10f) + p3 * logf(p3 + 1e-10f);
    }
    const float esum = block_reduce_sum1024(e, sh32);

    if (t == 0) {
        *out_loss = 0.25f * (tot / (float)((size_t)N_ROWS * D_DIM));
        *out_perp = expf(-esum);
    }
}

// ===========================================================================
extern "C" void kernel_launch(void* const* d_in, const int* in_sizes, int n_in,
                              void* d_out, int out_size) {
    const float* inputs   = (const float*)d_in[0];
    const float* codebook = (const float*)d_in[1];

    float* out       = (float*)d_out;
    float* out_loss  = out;
    float* out_quant = out + 1;
    float* out_probs = out_quant + (size_t)N_ROWS * D_DIM;
    float* out_perp  = out_probs + (size_t)N_ROWS * K_CB;
    float* out_idx   = out_perp + 1;

    cudaFuncSetAttribute(gemm_tc_kernel,
                         cudaFuncAttributeMaxDynamicSharedMemorySize, GEMM_SMEM);

    normalize_all_kernel<<<(K_CB + N_ROWS) / 8, 256>>>(inputs, codebook);

    dim3 grid(K_CB / 128, N_ROWS / 128);   // (32, 128)
    gemm_tc_kernel<<<grid, 256, GEMM_SMEM>>>();

    softmax_row_kernel<<<N_ROWS, 256>>>(out_probs, out_quant, out_idx);
    finalize_kernel<<<1, 1024>>>(out_loss, out_perp);
}